// round 4
// baseline (speedup 1.0000x reference)
#include <cuda_runtime.h>

// L1Loss: out = mean(|yhat - y|) over 64*128*4096 fp32 elements.
// R4: R1's proven mainloop config (2368 blocks x 256 thr, 2 waves, simple
// grid-stride float4 loop) fused with a last-block epilogue so the whole
// thing is ONE graph node (no zero-init kernel, no launch gap).

#define NBLOCKS 2368
#define NTHREADS 256

__device__ float g_partials[NBLOCKS];
__device__ unsigned int g_ticket = 0;   // atomicInc wraps at NBLOCKS-1 -> self-resetting per replay

__global__ void __launch_bounds__(NTHREADS) l1_reduce_kernel(
    const float4* __restrict__ a,
    const float4* __restrict__ b,
    float* __restrict__ out,
    int n4,            // number of float4 elements
    int n_tail,        // scalar elements after n4*4
    float inv_n)
{
    float acc = 0.0f;

    const int idx    = blockIdx.x * blockDim.x + threadIdx.x;
    const int stride = gridDim.x * blockDim.x;

    for (int i = idx; i < n4; i += stride) {
        float4 x = a[i];
        float4 y = b[i];
        acc += fabsf(x.x - y.x);
        acc += fabsf(x.y - y.y);
        acc += fabsf(x.z - y.z);
        acc += fabsf(x.w - y.w);
    }

    // Scalar tail (N not divisible by 4)
    if (blockIdx.x == 0 && threadIdx.x < n_tail) {
        const float* af = (const float*)a;
        const float* bf = (const float*)b;
        int t = n4 * 4 + threadIdx.x;
        acc += fabsf(af[t] - bf[t]);
    }

    // Intra-block reduction
    #pragma unroll
    for (int o = 16; o > 0; o >>= 1)
        acc += __shfl_down_sync(0xffffffffu, acc, o);

    __shared__ float smem[NTHREADS / 32];
    int lane = threadIdx.x & 31;
    int wid  = threadIdx.x >> 5;
    if (lane == 0) smem[wid] = acc;
    __syncthreads();

    __shared__ bool is_last;
    if (threadIdx.x == 0) {
        float v = 0.0f;
        #pragma unroll
        for (int w = 0; w < NTHREADS / 32; w++) v += smem[w];
        g_partials[blockIdx.x] = v;
        __threadfence();  // make partial visible before taking a ticket
        unsigned int t = atomicInc(&g_ticket, NBLOCKS - 1);
        is_last = (t == NBLOCKS - 1);
    }
    __syncthreads();

    // Last block to finish sums all partials and writes the result.
    if (is_last) {
        float v = 0.0f;
        for (int j = threadIdx.x; j < NBLOCKS; j += NTHREADS)
            v += g_partials[j];
        #pragma unroll
        for (int o = 16; o > 0; o >>= 1)
            v += __shfl_down_sync(0xffffffffu, v, o);
        if (lane == 0) smem[wid] = v;
        __syncthreads();
        if (threadIdx.x == 0) {
            float total = 0.0f;
            #pragma unroll
            for (int w = 0; w < NTHREADS / 32; w++) total += smem[w];
            out[0] = total * inv_n;
        }
    }
}

extern "C" void kernel_launch(void* const* d_in, const int* in_sizes, int n_in,
                              void* d_out, int out_size)
{
    const float* yhat = (const float*)d_in[0];
    const float* y    = (const float*)d_in[1];
    float* out = (float*)d_out;

    long long n = in_sizes[0];
    int n4 = (int)(n / 4);
    int n_tail = (int)(n - (long long)n4 * 4);
    float inv_n = 1.0f / (float)n;

    l1_reduce_kernel<<<NBLOCKS, NTHREADS>>>(
        (const float4*)yhat, (const float4*)y, out, n4, n_tail, inv_n);
}

// round 5
// speedup vs baseline: 1.0027x; 1.0027x over previous
#include <cuda_runtime.h>

// L1Loss: out = mean(|yhat - y|) over 64*128*4096 fp32 elements.
// R5: R1 mainloop (2368x256, 2 waves) + FENCE-FREE last-block epilogue.
// __threadfence() (gpu scope) emits CCTL.IVALL (full L1D flush) per block,
// which poisoned R3/R4. Replaced with atom.release.gpu.inc (orders the
// partial STG, no L1 flush) + __ldcg reads (L2-direct, no acquire needed).

#define NBLOCKS 2368
#define NTHREADS 256

__device__ float g_partials[NBLOCKS];
__device__ unsigned int g_ticket = 0;   // atom.inc wraps at NBLOCKS-1 -> self-resetting per replay

__global__ void __launch_bounds__(NTHREADS) l1_reduce_kernel(
    const float4* __restrict__ a,
    const float4* __restrict__ b,
    float* __restrict__ out,
    int n4,            // number of float4 elements
    int n_tail,        // scalar elements after n4*4
    float inv_n)
{
    float acc = 0.0f;

    const int idx    = blockIdx.x * blockDim.x + threadIdx.x;
    const int stride = gridDim.x * blockDim.x;

    for (int i = idx; i < n4; i += stride) {
        float4 x = a[i];
        float4 y = b[i];
        acc += fabsf(x.x - y.x);
        acc += fabsf(x.y - y.y);
        acc += fabsf(x.z - y.z);
        acc += fabsf(x.w - y.w);
    }

    // Scalar tail (N not divisible by 4)
    if (blockIdx.x == 0 && threadIdx.x < n_tail) {
        const float* af = (const float*)a;
        const float* bf = (const float*)b;
        int t = n4 * 4 + threadIdx.x;
        acc += fabsf(af[t] - bf[t]);
    }

    // Intra-block reduction
    #pragma unroll
    for (int o = 16; o > 0; o >>= 1)
        acc += __shfl_down_sync(0xffffffffu, acc, o);

    __shared__ float smem[NTHREADS / 32];
    int lane = threadIdx.x & 31;
    int wid  = threadIdx.x >> 5;
    if (lane == 0) smem[wid] = acc;
    __syncthreads();

    __shared__ bool is_last;
    if (threadIdx.x == 0) {
        float v = 0.0f;
        #pragma unroll
        for (int w = 0; w < NTHREADS / 32; w++) v += smem[w];
        g_partials[blockIdx.x] = v;   // plain STG (write-through to L2)

        // Release-scoped wrapping increment: orders the STG above before the
        // ticket becomes visible, WITHOUT a gpu-scope fence (no CCTL.IVALL).
        unsigned int t;
        asm volatile(
            "atom.release.gpu.global.inc.u32 %0, [%1], %2;"
            : "=r"(t)
            : "l"(&g_ticket), "r"((unsigned int)(NBLOCKS - 1))
            : "memory");
        is_last = (t == NBLOCKS - 1);
    }
    __syncthreads();

    // Last block to finish sums all partials (L2-direct reads) and writes out.
    if (is_last) {
        float v = 0.0f;
        for (int j = threadIdx.x; j < NBLOCKS; j += NTHREADS)
            v += __ldcg(&g_partials[j]);
        #pragma unroll
        for (int o = 16; o > 0; o >>= 1)
            v += __shfl_down_sync(0xffffffffu, v, o);
        if (lane == 0) smem[wid] = v;
        __syncthreads();
        if (threadIdx.x == 0) {
            float total = 0.0f;
            #pragma unroll
            for (int w = 0; w < NTHREADS / 32; w++) total += smem[w];
            out[0] = total * inv_n;
        }
    }
}

extern "C" void kernel_launch(void* const* d_in, const int* in_sizes, int n_in,
                              void* d_out, int out_size)
{
    const float* yhat = (const float*)d_in[0];
    const float* y    = (const float*)d_in[1];
    float* out = (float*)d_out;

    long long n = in_sizes[0];
    int n4 = (int)(n / 4);
    int n_tail = (int)(n - (long long)n4 * 4);
    float inv_n = 1.0f / (float)n;

    l1_reduce_kernel<<<NBLOCKS, NTHREADS>>>(
        (const float4*)yhat, (const float4*)y, out, n4, n_tail, inv_n);
}

// round 6
// speedup vs baseline: 1.0804x; 1.0775x over previous
#include <cuda_runtime.h>

// L1Loss: out = mean(|yhat - y|) over 64*128*4096 fp32 elements.
// R6: R1 mainloop + minimal-overhead single-kernel finish.
//  - per block: REDG atomicAdd of partial to g_acc (fire-and-forget, same as R1)
//  - thread 0 only: acq_rel ticket inc; NO trailing __syncthreads (warps exit free)
//  - last block: single __ldcg of g_acc -> out[0], reset g_acc for next replay.

#define NBLOCKS 2368
#define NTHREADS 256

__device__ float g_acc = 0.0f;
__device__ unsigned int g_ticket = 0;   // atom.inc wraps at NBLOCKS-1 -> self-resetting

__global__ void __launch_bounds__(NTHREADS) l1_reduce_kernel(
    const float4* __restrict__ a,
    const float4* __restrict__ b,
    float* __restrict__ out,
    int n4,            // number of float4 elements
    int n_tail,        // scalar elements after n4*4
    float inv_n)
{
    float acc = 0.0f;

    const int idx    = blockIdx.x * blockDim.x + threadIdx.x;
    const int stride = gridDim.x * blockDim.x;

    for (int i = idx; i < n4; i += stride) {
        float4 x = a[i];
        float4 y = b[i];
        acc += fabsf(x.x - y.x);
        acc += fabsf(x.y - y.y);
        acc += fabsf(x.z - y.z);
        acc += fabsf(x.w - y.w);
    }

    // Scalar tail (N not divisible by 4)
    if (blockIdx.x == 0 && threadIdx.x < n_tail) {
        const float* af = (const float*)a;
        const float* bf = (const float*)b;
        int t = n4 * 4 + threadIdx.x;
        acc += fabsf(af[t] - bf[t]);
    }

    // Intra-block reduction
    #pragma unroll
    for (int o = 16; o > 0; o >>= 1)
        acc += __shfl_down_sync(0xffffffffu, acc, o);

    __shared__ float smem[NTHREADS / 32];
    int lane = threadIdx.x & 31;
    int wid  = threadIdx.x >> 5;
    if (lane == 0) smem[wid] = acc;
    __syncthreads();
    // All warps except warp 0's thread 0 are DONE after this point and exit.

    if (threadIdx.x == 0) {
        float v = 0.0f;
        #pragma unroll
        for (int w = 0; w < NTHREADS / 32; w++) v += smem[w];

        // Fire-and-forget global accumulate (compiles to REDG, like R1).
        atomicAdd(&g_acc, v);

        // acq_rel ticket: release orders the REDG above before the ticket is
        // visible; acquire orders the __ldcg below after all prior releases.
        unsigned int t;
        asm volatile(
            "atom.acq_rel.gpu.global.inc.u32 %0, [%1], %2;"
            : "=r"(t)
            : "l"(&g_ticket), "r"((unsigned int)(NBLOCKS - 1))
            : "memory");

        if (t == NBLOCKS - 1) {
            float total = __ldcg(&g_acc);
            out[0] = total * inv_n;
            g_acc = 0.0f;   // reset for next graph replay (stream-serialized)
        }
    }
}

extern "C" void kernel_launch(void* const* d_in, const int* in_sizes, int n_in,
                              void* d_out, int out_size)
{
    const float* yhat = (const float*)d_in[0];
    const float* y    = (const float*)d_in[1];
    float* out = (float*)d_out;

    long long n = in_sizes[0];
    int n4 = (int)(n / 4);
    int n_tail = (int)(n - (long long)n4 * 4);
    float inv_n = 1.0f / (float)n;

    l1_reduce_kernel<<<NBLOCKS, NTHREADS>>>(
        (const float4*)yhat, (const float4*)y, out, n4, n_tail, inv_n);
}

// round 7
// speedup vs baseline: 1.0989x; 1.0171x over previous
#include <cuda_runtime.h>

// L1Loss: out = mean(|yhat - y|) over 64*128*4096 fp32 elements.
// R7: R1 mainloop + ONE fused atomic epilogue.
// Each block atomically adds (fixed_point_partial << 12) | 1 to a single u64:
//   low 12 bits  = completed-block count (2368 < 4096, never carries)
//   high 52 bits = sum of partials in 2^-20 fixed point (max ~2^45)
// The atomic's return value identifies the last block AND delivers the total,
// so there is no second atomic, no fence, and no ordering hazard.

#define NBLOCKS 2368
#define NTHREADS 256
#define FIX_SCALE 1048576.0   // 2^20

__device__ unsigned long long g_pack = 0ull;  // reset by last block each call

__global__ void __launch_bounds__(NTHREADS) l1_reduce_kernel(
    const float4* __restrict__ a,
    const float4* __restrict__ b,
    float* __restrict__ out,
    int n4,            // number of float4 elements
    int n_tail,        // scalar elements after n4*4
    float inv_n)
{
    float acc = 0.0f;

    const int idx    = blockIdx.x * blockDim.x + threadIdx.x;
    const int stride = gridDim.x * blockDim.x;

    for (int i = idx; i < n4; i += stride) {
        float4 x = a[i];
        float4 y = b[i];
        acc += fabsf(x.x - y.x);
        acc += fabsf(x.y - y.y);
        acc += fabsf(x.z - y.z);
        acc += fabsf(x.w - y.w);
    }

    // Scalar tail (N not divisible by 4)
    if (blockIdx.x == 0 && threadIdx.x < n_tail) {
        const float* af = (const float*)a;
        const float* bf = (const float*)b;
        int t = n4 * 4 + threadIdx.x;
        acc += fabsf(af[t] - bf[t]);
    }

    // Intra-block reduction
    #pragma unroll
    for (int o = 16; o > 0; o >>= 1)
        acc += __shfl_down_sync(0xffffffffu, acc, o);

    __shared__ float smem[NTHREADS / 32];
    int lane = threadIdx.x & 31;
    int wid  = threadIdx.x >> 5;
    if (lane == 0) smem[wid] = acc;
    __syncthreads();
    // Warps 1..7 (and warp 0 lanes 1..31) exit after this point.

    if (threadIdx.x == 0) {
        float v = 0.0f;
        #pragma unroll
        for (int w = 0; w < NTHREADS / 32; w++) v += smem[w];

        // Fixed-point encode: partial in 2^-20 units, count=1 in low 12 bits.
        unsigned long long fixed =
            (unsigned long long)__double2ll_rn((double)v * FIX_SCALE);
        unsigned long long pack = (fixed << 12) | 1ull;

        unsigned long long old = atomicAdd(&g_pack, pack);

        if ((old & 0xFFFull) == (unsigned long long)(NBLOCKS - 1)) {
            // We are the last block; total = old + our contribution.
            unsigned long long total_fixed = (old + pack) >> 12;
            double total = (double)(long long)total_fixed * (1.0 / FIX_SCALE);
            out[0] = (float)(total * (double)inv_n);
            g_pack = 0ull;   // reset for next graph replay (all peers done)
        }
    }
}

extern "C" void kernel_launch(void* const* d_in, const int* in_sizes, int n_in,
                              void* d_out, int out_size)
{
    const float* yhat = (const float*)d_in[0];
    const float* y    = (const float*)d_in[1];
    float* out = (float*)d_out;

    long long n = in_sizes[0];
    int n4 = (int)(n / 4);
    int n_tail = (int)(n - (long long)n4 * 4);
    float inv_n = 1.0f / (float)n;

    l1_reduce_kernel<<<NBLOCKS, NTHREADS>>>(
        (const float4*)yhat, (const float4*)y, out, n4, n_tail, inv_n);
}